// round 1
// baseline (speedup 1.0000x reference)
#include <cuda_runtime.h>
#include <cuda_bf16.h>

// Problem constants (fixed shapes per reference setup_inputs)
#define B_   32
#define C_   4
#define P_   (360 * 640)      // 230400
#define L_   5
#define NVEC (P_ / 4)         // 57600 vec4 groups per batch

#define DELTA_V 1.0f
#define DELTA_D 6.0f

// ---- scratch (no device allocation allowed) ----
__device__ float g_sums[B_ * L_ * C_];     // [B][L][C]
__device__ int   g_counts[B_ * L_];        // [B][L]
__device__ float g_means[B_ * (L_ + 1) * C_]; // [B][6][4], lane 0 = zeros
__device__ int   g_valid[B_ * (L_ + 1)];   // [B][6], lane 0 = 0
__device__ float g_scalars[4];             // 0: dist_sum, 1: point_count, 2: var_loss

// --------------------------------------------------------------------------
__global__ void zero_kernel() {
    int i = blockIdx.x * blockDim.x + threadIdx.x;
    if (i < B_ * L_ * C_) g_sums[i] = 0.0f;
    if (i < B_ * L_)      g_counts[i] = 0;
    if (i < 4)            g_scalars[i] = 0.0f;
}

// --------------------------------------------------------------------------
// Pass 1: per-(batch, lane) counts and channel sums.
// grid = (NB, B_), block = 256. 128-bit loads, register accumulation,
// predicated adds (no register-indexed arrays -> no local spills).
__global__ void accum_kernel(const int* __restrict__ tg,
                             const float* __restrict__ emb) {
    const int b = blockIdx.y;
    const int4*   t4 = (const int4*)(tg + (size_t)b * P_);
    const float4* e4 = (const float4*)(emb + (size_t)b * C_ * P_);

    float s[L_][C_];
    int cnt[L_];
#pragma unroll
    for (int l = 0; l < L_; l++) {
        cnt[l] = 0;
#pragma unroll
        for (int c = 0; c < C_; c++) s[l][c] = 0.0f;
    }

    for (int i = blockIdx.x * blockDim.x + threadIdx.x; i < NVEC;
         i += gridDim.x * blockDim.x) {
        int4 tv = t4[i];
        float4 ev[C_];
#pragma unroll
        for (int c = 0; c < C_; c++) ev[c] = e4[(size_t)c * NVEC + i];

        int tj[4] = {tv.x, tv.y, tv.z, tv.w};
#pragma unroll
        for (int j = 0; j < 4; j++) {
            const int tt = tj[j];
#pragma unroll
            for (int l = 0; l < L_; l++) {
                const bool m = (tt == l + 1);
                cnt[l] += m ? 1 : 0;
                const float fm = m ? 1.0f : 0.0f;
#pragma unroll
                for (int c = 0; c < C_; c++)
                    s[l][c] = fmaf(fm, ((const float*)&ev[c])[j], s[l][c]);
            }
        }
    }

    // warp reduce
#pragma unroll
    for (int l = 0; l < L_; l++) {
#pragma unroll
        for (int off = 16; off > 0; off >>= 1) {
            cnt[l] += __shfl_down_sync(0xffffffffu, cnt[l], off);
#pragma unroll
            for (int c = 0; c < C_; c++)
                s[l][c] += __shfl_down_sync(0xffffffffu, s[l][c], off);
        }
    }

    __shared__ float ss[L_ * C_];
    __shared__ int   sc[L_];
    if (threadIdx.x < L_ * C_) ss[threadIdx.x] = 0.0f;
    if (threadIdx.x < L_)      sc[threadIdx.x] = 0;
    __syncthreads();

    if ((threadIdx.x & 31) == 0) {
#pragma unroll
        for (int l = 0; l < L_; l++) {
            atomicAdd(&sc[l], cnt[l]);
#pragma unroll
            for (int c = 0; c < C_; c++) atomicAdd(&ss[l * C_ + c], s[l][c]);
        }
    }
    __syncthreads();

    if (threadIdx.x < L_ * C_)
        atomicAdd(&g_sums[b * L_ * C_ + threadIdx.x], ss[threadIdx.x]);
    if (threadIdx.x < L_)
        atomicAdd(&g_counts[b * L_ + threadIdx.x], sc[threadIdx.x]);
}

// --------------------------------------------------------------------------
// Means, validity, point_count, and the full push (distance) loss.
// 1 warp, thread b handles batch b.
__global__ void means_kernel() {
    const int b = threadIdx.x;  // 0..31

    float mean[L_][C_];
    int   vld[L_];
    float pc_local = 0.0f;

#pragma unroll
    for (int l = 0; l < L_; l++) {
        const int c = g_counts[b * L_ + l];
        vld[l] = (c > 1);
        const float inv = 1.0f / (float)max(c, 1);
#pragma unroll
        for (int ch = 0; ch < C_; ch++) {
            const float m = g_sums[(b * L_ + l) * C_ + ch] * inv;
            mean[l][ch] = m;
            g_means[(b * (L_ + 1) + (l + 1)) * C_ + ch] = m;
        }
        g_valid[b * (L_ + 1) + (l + 1)] = vld[l];
        if (vld[l]) pc_local += (float)c;
    }
#pragma unroll
    for (int ch = 0; ch < C_; ch++) g_means[b * (L_ + 1) * C_ + ch] = 0.0f;
    g_valid[b * (L_ + 1)] = 0;

    // push loss over lane pairs (i < j, both valid)
    float psum = 0.0f;
    int npairs = 0;
#pragma unroll
    for (int i = 0; i < L_; i++) {
#pragma unroll
        for (int j = i + 1; j < L_; j++) {
            if (vld[i] && vld[j]) {
                float sq = 0.0f;
#pragma unroll
                for (int ch = 0; ch < C_; ch++) {
                    const float d = mean[i][ch] - mean[j][ch];
                    sq = fmaf(d, d, sq);
                }
                const float pd = sqrtf(fmaxf(sq, 1e-12f));
                const float ph = fmaxf(DELTA_D - pd, 0.0f);
                psum += ph * ph;
                npairs++;
            }
        }
    }
    const float var_b = (npairs > 0) ? psum / (float)npairs : 0.0f;
    const float has   = (npairs > 0) ? 1.0f : 0.0f;

    float var_sum = var_b, nb = has, pc = pc_local;
#pragma unroll
    for (int off = 16; off > 0; off >>= 1) {
        var_sum += __shfl_down_sync(0xffffffffu, var_sum, off);
        nb      += __shfl_down_sync(0xffffffffu, nb, off);
        pc      += __shfl_down_sync(0xffffffffu, pc, off);
    }
    if (threadIdx.x == 0) {
        g_scalars[1] = pc;
        g_scalars[2] = (nb > 0.0f) ? var_sum / fmaxf(nb, 1.0f) : 0.0f;
    }
}

// --------------------------------------------------------------------------
// Pass 2: per-point pull hinge^2. Means cached in shared; one global
// atomic per block.
__global__ void dist_kernel(const int* __restrict__ tg,
                            const float* __restrict__ emb) {
    const int b = blockIdx.y;
    __shared__ float sm[(L_ + 1) * C_];
    __shared__ int   sv[L_ + 1];
    if (threadIdx.x < (L_ + 1) * C_) sm[threadIdx.x] = g_means[b * (L_ + 1) * C_ + threadIdx.x];
    if (threadIdx.x < (L_ + 1))      sv[threadIdx.x] = g_valid[b * (L_ + 1) + threadIdx.x];
    __syncthreads();

    const int4*   t4 = (const int4*)(tg + (size_t)b * P_);
    const float4* e4 = (const float4*)(emb + (size_t)b * C_ * P_);

    float local = 0.0f;
    for (int i = blockIdx.x * blockDim.x + threadIdx.x; i < NVEC;
         i += gridDim.x * blockDim.x) {
        int4 tv = t4[i];
        float4 ev[C_];
#pragma unroll
        for (int c = 0; c < C_; c++) ev[c] = e4[(size_t)c * NVEC + i];

        int tj[4] = {tv.x, tv.y, tv.z, tv.w};
#pragma unroll
        for (int j = 0; j < 4; j++) {
            const int tt = tj[j];
            if (sv[tt]) {
                float sq = 0.0f;
#pragma unroll
                for (int c = 0; c < C_; c++) {
                    const float d = ((const float*)&ev[c])[j] - sm[tt * C_ + c];
                    sq = fmaf(d, d, sq);
                }
                const float dist = sqrtf(fmaxf(sq, 1e-12f));
                const float h = dist - DELTA_V;
                if (h > 0.0f) local = fmaf(h, h, local);
            }
        }
    }

    // warp reduce
#pragma unroll
    for (int off = 16; off > 0; off >>= 1)
        local += __shfl_down_sync(0xffffffffu, local, off);

    __shared__ float sred;
    if (threadIdx.x == 0) sred = 0.0f;
    __syncthreads();
    if ((threadIdx.x & 31) == 0) atomicAdd(&sred, local);
    __syncthreads();
    if (threadIdx.x == 0) atomicAdd(&g_scalars[0], sred);
}

// --------------------------------------------------------------------------
__global__ void finalize_kernel(float* __restrict__ out) {
    const float ds = g_scalars[0];
    const float pc = g_scalars[1];
    const float dist_loss = (pc > 0.0f) ? ds / fmaxf(pc, 1.0f) : 0.0f;
    out[0] = dist_loss + g_scalars[2];
}

// --------------------------------------------------------------------------
extern "C" void kernel_launch(void* const* d_in, const int* in_sizes, int n_in,
                              void* d_out, int out_size) {
    const int*   tg  = (const int*)d_in[0];    // targets [32,360,640] int32
    const float* emb = (const float*)d_in[1];  // embedding [32,4,360,640] f32
    float* out = (float*)d_out;

    const int NB = 60;               // blocks per batch for the big passes
    dim3 grid(NB, B_);

    zero_kernel<<<1, 1024>>>();
    accum_kernel<<<grid, 256>>>(tg, emb);
    means_kernel<<<1, 32>>>();
    dist_kernel<<<grid, 256>>>(tg, emb);
    finalize_kernel<<<1, 1>>>(out);
}